// round 1
// baseline (speedup 1.0000x reference)
#include <cuda_runtime.h>
#include <cuda_bf16.h>
#include <math.h>

// Problem constants
#define SEQ   4096
#define DM    1024
#define NH    16
#define DH    64

// ---------------- scratch (no allocations allowed) ----------------
__device__ float g_Q[SEQ * DM];
__device__ float g_K[SEQ * DM];
__device__ float g_V[SEQ * DM];
__device__ float g_A[SEQ * DM];   // attention output (pre-proj)

// ---------------- NT GEMM: C[m,n] = sum_k A[m,k] * B[n,k] ----------------
// M=4096, N=1024, K=1024 hardcoded. BM=BN=128, BK=16, 256 threads, 8x8/thread.
#define GBM 128
#define GBN 128
#define GBK 16
#define GST 132   // padded smem row stride (floats); 132*4=528 bytes, 16B aligned

__device__ __forceinline__ void gemm_nt_tile(const float* __restrict__ A,
                                             const float* __restrict__ B,
                                             float* __restrict__ C) {
    __shared__ float As[GBK * GST];
    __shared__ float Bs[GBK * GST];

    const int t  = threadIdx.x;
    const int tr = t >> 4;        // 0..15 -> row group
    const int tc = t & 15;        // 0..15 -> col group
    const int m0 = blockIdx.y * GBM;
    const int n0 = blockIdx.x * GBN;

    float acc[8][8];
#pragma unroll
    for (int i = 0; i < 8; i++)
#pragma unroll
        for (int j = 0; j < 8; j++) acc[i][j] = 0.f;

    for (int k0 = 0; k0 < DM; k0 += GBK) {
        // Load 128x16 A and B tiles (transposed into smem: As[k][m])
#pragma unroll
        for (int l = 0; l < 2; l++) {
            int idx = t + l * 256;          // 0..511
            int row = idx >> 2;             // 0..127
            int kq  = (idx & 3) << 2;       // 0,4,8,12
            float4 va = *(const float4*)&A[(size_t)(m0 + row) * DM + k0 + kq];
            As[(kq + 0) * GST + row] = va.x;
            As[(kq + 1) * GST + row] = va.y;
            As[(kq + 2) * GST + row] = va.z;
            As[(kq + 3) * GST + row] = va.w;
            float4 vb = *(const float4*)&B[(size_t)(n0 + row) * DM + k0 + kq];
            Bs[(kq + 0) * GST + row] = vb.x;
            Bs[(kq + 1) * GST + row] = vb.y;
            Bs[(kq + 2) * GST + row] = vb.z;
            Bs[(kq + 3) * GST + row] = vb.w;
        }
        __syncthreads();

#pragma unroll
        for (int kk = 0; kk < GBK; kk++) {
            float4 a0 = *(float4*)&As[kk * GST + tr * 8];
            float4 a1 = *(float4*)&As[kk * GST + tr * 8 + 4];
            float4 b0 = *(float4*)&Bs[kk * GST + tc * 8];
            float4 b1 = *(float4*)&Bs[kk * GST + tc * 8 + 4];
            float av[8] = {a0.x, a0.y, a0.z, a0.w, a1.x, a1.y, a1.z, a1.w};
            float bv[8] = {b0.x, b0.y, b0.z, b0.w, b1.x, b1.y, b1.z, b1.w};
#pragma unroll
            for (int i = 0; i < 8; i++)
#pragma unroll
                for (int j = 0; j < 8; j++) acc[i][j] = fmaf(av[i], bv[j], acc[i][j]);
        }
        __syncthreads();
    }

#pragma unroll
    for (int i = 0; i < 8; i++) {
        int gr = m0 + tr * 8 + i;
        float4 c0v = make_float4(acc[i][0], acc[i][1], acc[i][2], acc[i][3]);
        float4 c1v = make_float4(acc[i][4], acc[i][5], acc[i][6], acc[i][7]);
        *(float4*)&C[(size_t)gr * DM + n0 + tc * 8]     = c0v;
        *(float4*)&C[(size_t)gr * DM + n0 + tc * 8 + 4] = c1v;
    }
}

__global__ __launch_bounds__(256, 2)
void qkv_kernel(const float* __restrict__ x,
                const float* __restrict__ Wq,
                const float* __restrict__ Wk,
                const float* __restrict__ Wv) {
    const float* B = (blockIdx.z == 0) ? Wq : (blockIdx.z == 1 ? Wk : Wv);
    float* C = (blockIdx.z == 0) ? g_Q : (blockIdx.z == 1 ? g_K : g_V);
    gemm_nt_tile(x, B, C);
}

__global__ __launch_bounds__(256, 2)
void proj_kernel(const float* __restrict__ Wo, float* __restrict__ out) {
    gemm_nt_tile(g_A, Wo, out);
}

// ---------------- RoPE (in-place on g_Q, g_K) ----------------
// One block per sequence position; 32 double-precision sincos shared by all heads.
__global__ void rope_kernel() {
    __shared__ float cs[32], sn[32];
    const int s = blockIdx.x;
    const int t = threadIdx.x;
    if (t < 32) {
        double invf = pow(10000.0, -((double)(2 * t)) / 64.0);
        double ang  = (double)s * invf;
        double si, co;
        sincos(ang, &si, &co);
        cs[t] = (float)co;
        sn[t] = (float)si;
    }
    __syncthreads();
    for (int idx = t; idx < NH * 32; idx += 256) {
        int h = idx >> 5;
        int i = idx & 31;
        int base = s * DM + h * DH + i;
        float c = cs[i], si = sn[i];
        float q1 = g_Q[base], q2 = g_Q[base + 32];
        g_Q[base]      = q1 * c - q2 * si;
        g_Q[base + 32] = q2 * c + q1 * si;
        float k1 = g_K[base], k2 = g_K[base + 32];
        g_K[base]      = k1 * c - k2 * si;
        g_K[base + 32] = k2 * c + k1 * si;
    }
}

// ---------------- Flash attention (causal, online softmax) ----------------
// Block = (q-tile of 64 rows, head). 256 threads as 16x16; each thread owns a
// 4x4 fragment. Smem: Qs[d][r], Ks[d][c] (reused as Ps[c][r]), Vs[c][dv].
#define FBM 64
#define FBN 64
#define FST 68                       // padded stride (floats); 68*4=272, 16B aligned
#define FLASH_SMEM (3 * DH * FST * 4)

__global__ __launch_bounds__(256)
void flash_kernel() {
    extern __shared__ float sm[];
    float* Qs  = sm;                  // [DH][FST]  d-major
    float* KPs = sm + DH * FST;       // [DH][FST]  d-major K; reused as P[c][r]
    float* Vs  = sm + 2 * DH * FST;   // [FBN][FST] c-major, dv contiguous

    const int h     = blockIdx.y;
    const int qt    = (int)gridDim.x - 1 - (int)blockIdx.x;  // heavy tiles first
    const int qbase = qt * FBM;
    const int t     = threadIdx.x;
    const int tyy   = t >> 4;
    const int txx   = t & 15;
    const int r0    = tyy * 4;
    const int c0    = txx * 4;

    // Load Q tile, scaled by 1/sqrt(Dh)
#pragma unroll
    for (int l = 0; l < 4; l++) {
        int idx = t + l * 256;            // 0..1023 = 64 rows x 16 float4
        int r   = idx >> 4;
        int d4  = (idx & 15) << 2;
        float4 v = *(const float4*)&g_Q[(size_t)(qbase + r) * DM + h * DH + d4];
        Qs[(d4 + 0) * FST + r] = v.x * 0.125f;
        Qs[(d4 + 1) * FST + r] = v.y * 0.125f;
        Qs[(d4 + 2) * FST + r] = v.z * 0.125f;
        Qs[(d4 + 3) * FST + r] = v.w * 0.125f;
    }

    float m_i[4], l_i[4], o[4][4];
#pragma unroll
    for (int i = 0; i < 4; i++) {
        m_i[i] = -1e30f; l_i[i] = 0.f;
#pragma unroll
        for (int j = 0; j < 4; j++) o[i][j] = 0.f;
    }

    const int ntiles = qt + 1;
    for (int kt = 0; kt < ntiles; kt++) {
        const int kbase = kt * FBN;
        __syncthreads();   // prev iter done with KPs/Vs (also covers Qs load, iter 0)

        // Load K (d-major) and V (c-major) tiles
#pragma unroll
        for (int l = 0; l < 4; l++) {
            int idx = t + l * 256;
            int c   = idx >> 4;
            int d4  = (idx & 15) << 2;
            float4 kv = *(const float4*)&g_K[(size_t)(kbase + c) * DM + h * DH + d4];
            KPs[(d4 + 0) * FST + c] = kv.x;
            KPs[(d4 + 1) * FST + c] = kv.y;
            KPs[(d4 + 2) * FST + c] = kv.z;
            KPs[(d4 + 3) * FST + c] = kv.w;
            float4 vv = *(const float4*)&g_V[(size_t)(kbase + c) * DM + h * DH + d4];
            *(float4*)&Vs[c * FST + d4] = vv;
        }
        __syncthreads();

        // S = (Q*scale) K^T   (4x4 fragment per thread)
        float s[4][4];
#pragma unroll
        for (int i = 0; i < 4; i++)
#pragma unroll
            for (int j = 0; j < 4; j++) s[i][j] = 0.f;
#pragma unroll 8
        for (int d = 0; d < DH; d++) {
            float4 a = *(float4*)&Qs[d * FST + r0];
            float4 b = *(float4*)&KPs[d * FST + c0];
            float av[4] = {a.x, a.y, a.z, a.w};
            float bv[4] = {b.x, b.y, b.z, b.w};
#pragma unroll
            for (int i = 0; i < 4; i++)
#pragma unroll
                for (int j = 0; j < 4; j++) s[i][j] = fmaf(av[i], bv[j], s[i][j]);
        }

        // Causal mask only on the diagonal tile
        if (kt == qt) {
#pragma unroll
            for (int i = 0; i < 4; i++)
#pragma unroll
                for (int j = 0; j < 4; j++)
                    if (c0 + j > r0 + i) s[i][j] = -1e30f;
        }

        // Online softmax: row reductions across the 16 threads sharing tyy
        float mnew[4], alpha[4], rs[4];
#pragma unroll
        for (int i = 0; i < 4; i++) {
            float mx = fmaxf(fmaxf(s[i][0], s[i][1]), fmaxf(s[i][2], s[i][3]));
            mx = fmaxf(mx, __shfl_xor_sync(0xffffffffu, mx, 1));
            mx = fmaxf(mx, __shfl_xor_sync(0xffffffffu, mx, 2));
            mx = fmaxf(mx, __shfl_xor_sync(0xffffffffu, mx, 4));
            mx = fmaxf(mx, __shfl_xor_sync(0xffffffffu, mx, 8));
            mnew[i]  = fmaxf(m_i[i], mx);
            alpha[i] = __expf(m_i[i] - mnew[i]);
            rs[i] = 0.f;
        }
#pragma unroll
        for (int i = 0; i < 4; i++) {
#pragma unroll
            for (int j = 0; j < 4; j++) {
                float p = __expf(s[i][j] - mnew[i]);
                s[i][j] = p;
                rs[i] += p;
            }
        }
#pragma unroll
        for (int i = 0; i < 4; i++) {
            rs[i] += __shfl_xor_sync(0xffffffffu, rs[i], 1);
            rs[i] += __shfl_xor_sync(0xffffffffu, rs[i], 2);
            rs[i] += __shfl_xor_sync(0xffffffffu, rs[i], 4);
            rs[i] += __shfl_xor_sync(0xffffffffu, rs[i], 8);
            l_i[i] = l_i[i] * alpha[i] + rs[i];
            m_i[i] = mnew[i];
#pragma unroll
            for (int j = 0; j < 4; j++) o[i][j] *= alpha[i];
        }

        __syncthreads();   // everyone done reading K before overwrite with P
        // Write P transposed: KPs[c][r]
#pragma unroll
        for (int i = 0; i < 4; i++)
#pragma unroll
            for (int j = 0; j < 4; j++)
                KPs[(c0 + j) * FST + (r0 + i)] = s[i][j];
        __syncthreads();

        // O += P V   (thread owns rows r0..r0+3, dv cols c0..c0+3)
#pragma unroll 8
        for (int c = 0; c < FBN; c++) {
            float4 a = *(float4*)&KPs[c * FST + r0];
            float4 b = *(float4*)&Vs[c * FST + c0];
            float av[4] = {a.x, a.y, a.z, a.w};
            float bv[4] = {b.x, b.y, b.z, b.w};
#pragma unroll
            for (int i = 0; i < 4; i++)
#pragma unroll
                for (int j = 0; j < 4; j++) o[i][j] = fmaf(av[i], bv[j], o[i][j]);
        }
    }

    // Epilogue: normalize and store
#pragma unroll
    for (int i = 0; i < 4; i++) {
        float inv = 1.f / l_i[i];
        float4 v = make_float4(o[i][0] * inv, o[i][1] * inv, o[i][2] * inv, o[i][3] * inv);
        *(float4*)&g_A[(size_t)(qbase + r0 + i) * DM + h * DH + c0] = v;
    }
}

// ---------------- launch ----------------
extern "C" void kernel_launch(void* const* d_in, const int* in_sizes, int n_in,
                              void* d_out, int out_size) {
    const float* x  = (const float*)d_in[0];
    const float* Wq = (const float*)d_in[1];
    const float* Wk = (const float*)d_in[2];
    const float* Wv = (const float*)d_in[3];
    const float* Wo = (const float*)d_in[4];
    float* out = (float*)d_out;

    // 52KB dynamic smem > 48KB default: raise the cap (idempotent, capture-safe)
    cudaFuncSetAttribute(flash_kernel, cudaFuncAttributeMaxDynamicSharedMemorySize,
                         FLASH_SMEM);

    dim3 gqkv(DM / GBN, SEQ / GBM, 3);       // (8, 32, 3)
    qkv_kernel<<<gqkv, 256>>>(x, Wq, Wk, Wv);

    rope_kernel<<<SEQ, 256>>>();

    dim3 gfl(SEQ / FBM, NH);                  // (64, 16)
    flash_kernel<<<gfl, 256, FLASH_SMEM>>>();

    dim3 gpr(DM / GBN, SEQ / GBM, 1);         // (8, 32)
    proj_kernel<<<gpr, 256>>>(Wo, out);
}

// round 3
// speedup vs baseline: 2.8576x; 2.8576x over previous
#include <cuda_runtime.h>
#include <cuda_bf16.h>
#include <math.h>
#include <stdint.h>

// Problem constants
#define SEQ   4096
#define DM    1024
#define NH    16
#define DH    64

// ---------------- scratch (no allocations allowed) ----------------
__device__ float g_Q[SEQ * DM];
__device__ float g_K[SEQ * DM];
__device__ float g_V[SEQ * DM];

__device__ __nv_bfloat16 g_xh[SEQ * DM],  g_xl[SEQ * DM];
__device__ __nv_bfloat16 g_wh[3 * DM * DM], g_wl[3 * DM * DM];   // Wq,Wk,Wv stacked rows
__device__ __nv_bfloat16 g_woh[DM * DM],  g_wol[DM * DM];
__device__ __nv_bfloat16 g_qh[SEQ * DM],  g_ql[SEQ * DM];        // roped, pre-scaled 1/8
__device__ __nv_bfloat16 g_kh[SEQ * DM],  g_kl[SEQ * DM];
__device__ __nv_bfloat16 g_vh[SEQ * DM],  g_vl[SEQ * DM];
__device__ __nv_bfloat16 g_ah[SEQ * DM],  g_al[SEQ * DM];        // attention out split

// ---------------- low-level helpers ----------------
__device__ __forceinline__ uint32_t smem_u32(const void* p) {
    uint32_t a;
    asm("{ .reg .u64 t; cvta.to.shared.u64 t, %1; cvt.u32.u64 %0, t; }" : "=r"(a) : "l"(p));
    return a;
}
__device__ __forceinline__ void cp_async16(uint32_t sa, const void* ga) {
    asm volatile("cp.async.cg.shared.global [%0], [%1], 16;" :: "r"(sa), "l"(ga));
}
#define CP_COMMIT() asm volatile("cp.async.commit_group;" ::: "memory")
#define CP_WAIT1()  asm volatile("cp.async.wait_group 1;" ::: "memory")
#define CP_WAIT0()  asm volatile("cp.async.wait_group 0;" ::: "memory")

__device__ __forceinline__ void ldsm_x4(uint32_t* r, uint32_t addr) {
    asm volatile("ldmatrix.sync.aligned.m8n8.x4.shared.b16 {%0,%1,%2,%3}, [%4];"
        : "=r"(r[0]), "=r"(r[1]), "=r"(r[2]), "=r"(r[3]) : "r"(addr));
}
__device__ __forceinline__ void ldsm_x4t(uint32_t* r, uint32_t addr) {
    asm volatile("ldmatrix.sync.aligned.m8n8.x4.trans.shared.b16 {%0,%1,%2,%3}, [%4];"
        : "=r"(r[0]), "=r"(r[1]), "=r"(r[2]), "=r"(r[3]) : "r"(addr));
}
__device__ __forceinline__ void mma16816(float* d, const uint32_t* a, const uint32_t* b) {
    asm volatile("mma.sync.aligned.m16n8k16.row.col.f32.bf16.bf16.f32 "
        "{%0,%1,%2,%3}, {%4,%5,%6,%7}, {%8,%9}, {%0,%1,%2,%3};"
        : "+f"(d[0]), "+f"(d[1]), "+f"(d[2]), "+f"(d[3])
        : "r"(a[0]), "r"(a[1]), "r"(a[2]), "r"(a[3]), "r"(b[0]), "r"(b[1]));
}
__device__ __forceinline__ uint32_t pack2(__nv_bfloat16 a, __nv_bfloat16 b) {
    __nv_bfloat162 t; t.x = a; t.y = b;
    uint32_t u; memcpy(&u, &t, 4); return u;
}
__device__ __forceinline__ void split1(float v, __nv_bfloat16& h, __nv_bfloat16& l) {
    h = __float2bfloat16(v);
    l = __float2bfloat16(v - __bfloat162float(h));
}

// ---------------- hi/lo convert kernel (inputs) ----------------
__global__ void cvt_kernel(const float* __restrict__ src, int sel) {
    __nv_bfloat16 *hi, *lo;
    switch (sel) {
        case 0: hi = g_xh;               lo = g_xl;               break;
        case 1: hi = g_wh;               lo = g_wl;               break;
        case 2: hi = g_wh + DM * DM;     lo = g_wl + DM * DM;     break;
        case 3: hi = g_wh + 2 * DM * DM; lo = g_wl + 2 * DM * DM; break;
        default: hi = g_woh;             lo = g_wol;              break;
    }
    int i = (blockIdx.x * 256 + threadIdx.x) * 4;
    float4 v = *(const float4*)&src[i];
    __nv_bfloat16 h0, l0, h1, l1, h2, l2, h3, l3;
    split1(v.x, h0, l0); split1(v.y, h1, l1);
    split1(v.z, h2, l2); split1(v.w, h3, l3);
    *(uint32_t*)&hi[i]     = pack2(h0, h1);
    *(uint32_t*)&hi[i + 2] = pack2(h2, h3);
    *(uint32_t*)&lo[i]     = pack2(l0, l1);
    *(uint32_t*)&lo[i + 2] = pack2(l2, l3);
}

// ---------------- HMMA split-bf16 NT GEMM ----------------
// C[m,n] = sum_k A[m,k]*B[n,k]; BM=BN=128, BK=64, 128 threads, 4 warps of 64x64.
#define SKB 144                    // smem row stride bytes (72 bf16, conflict-free ldsm)
#define GTILE (128 * SKB)          // 18432 B per matrix tile
#define GSTAGE (2 * GTILE)         // A+B
#define GEMM_SMEM (2 * GSTAGE)     // double buffer: 73728

__device__ __forceinline__ void gemm_issue(int t, uint32_t st,
                                           const __nv_bfloat16* A, const __nv_bfloat16* B) {
#pragma unroll
    for (int i = 0; i < 8; i++) {
        int idx = t + i * 128;
        int row = idx >> 3, ch = idx & 7;
        cp_async16(st + row * SKB + ch * 16,
                   (const char*)A + (size_t)row * (DM * 2) + ch * 16);
        cp_async16(st + GTILE + row * SKB + ch * 16,
                   (const char*)B + (size_t)row * (DM * 2) + ch * 16);
    }
    CP_COMMIT();
}

__global__ __launch_bounds__(128)
void mma_gemm_kernel(int which, float* __restrict__ outp) {
    extern __shared__ char dsm[];
    const uint32_t sbase = smem_u32(dsm);
    const int t = threadIdx.x, lane = t & 31, wid = t >> 5;
    const int nt = blockIdx.x, mt = blockIdx.y;
    const int m0 = mt * 128, n0 = nt * 128;

    const __nv_bfloat16 *pA[3], *pB[3];
    float* C; int ccol;
    if (which == 0) {
        pA[0] = g_xh; pA[1] = g_xh; pA[2] = g_xl;
        const __nv_bfloat16* bh = g_wh + (size_t)n0 * DM;
        const __nv_bfloat16* bl = g_wl + (size_t)n0 * DM;
        pB[0] = bh; pB[1] = bl; pB[2] = bh;
        int mat = nt >> 3;
        C = (mat == 0) ? g_Q : (mat == 1 ? g_K : g_V);
        ccol = (nt & 7) * 128;
    } else {
        pA[0] = g_ah; pA[1] = g_ah; pA[2] = g_al;
        const __nv_bfloat16* bh = g_woh + (size_t)n0 * DM;
        const __nv_bfloat16* bl = g_wol + (size_t)n0 * DM;
        pB[0] = bh; pB[1] = bl; pB[2] = bh;
        C = outp; ccol = n0;
    }

    float acc[4][8][4];
#pragma unroll
    for (int a = 0; a < 4; a++)
#pragma unroll
        for (int b = 0; b < 8; b++)
#pragma unroll
            for (int c = 0; c < 4; c++) acc[a][b][c] = 0.f;

    // prologue: chunks 0,1
#pragma unroll
    for (int c = 0; c < 2; c++) {
        int pass = c >> 4, k0 = (c & 15) * 64;
        gemm_issue(t, sbase + (c & 1) * GSTAGE,
                   pA[pass] + (size_t)m0 * DM + k0, pB[pass] + k0);
    }

    const int wm = wid & 1, wn = wid >> 1;      // 2x2 warps, 64x64 each
    const int q = lane >> 3, r = lane & 7;

    for (int c = 0; c < 48; c++) {
        if (c + 1 < 48) { CP_WAIT1(); } else { CP_WAIT0(); }
        __syncthreads();

        const uint32_t sa = sbase + (c & 1) * GSTAGE + (wm * 64) * SKB;
        const uint32_t sb = sbase + (c & 1) * GSTAGE + GTILE + (wn * 64) * SKB;
#pragma unroll
        for (int ks = 0; ks < 4; ks++) {
            uint32_t af[4][4], bf[4][4];
#pragma unroll
            for (int mb = 0; mb < 4; mb++)
                ldsm_x4(af[mb], sa + (mb * 16 + (q & 1) * 8 + r) * SKB
                                   + (ks * 16 + (q >> 1) * 8) * 2);
#pragma unroll
            for (int np = 0; np < 4; np++)
                ldsm_x4(bf[np], sb + (np * 16 + (q >> 1) * 8 + r) * SKB
                                   + (ks * 16 + (q & 1) * 8) * 2);
#pragma unroll
            for (int mb = 0; mb < 4; mb++)
#pragma unroll
                for (int np = 0; np < 4; np++) {
                    mma16816(acc[mb][np * 2],     af[mb], &bf[np][0]);
                    mma16816(acc[mb][np * 2 + 1], af[mb], &bf[np][2]);
                }
        }
        __syncthreads();
        if (c + 2 < 48) {
            int cn = c + 2, pass = cn >> 4, k0 = (cn & 15) * 64;
            gemm_issue(t, sbase + (cn & 1) * GSTAGE,
                       pA[pass] + (size_t)m0 * DM + k0, pB[pass] + k0);
        }
    }

    const int rr = lane >> 2, c2 = (lane & 3) * 2;
#pragma unroll
    for (int mb = 0; mb < 4; mb++) {
        int row0 = m0 + wm * 64 + mb * 16 + rr;
#pragma unroll
        for (int nb = 0; nb < 8; nb++) {
            int col = ccol + wn * 64 + nb * 8 + c2;
            *(float2*)&C[(size_t)row0 * DM + col]       = make_float2(acc[mb][nb][0], acc[mb][nb][1]);
            *(float2*)&C[(size_t)(row0 + 8) * DM + col] = make_float2(acc[mb][nb][2], acc[mb][nb][3]);
        }
    }
}

// ---------------- RoPE + bf16 split (Q scaled by 1/8) + V split ----------------
__global__ void rope_cvt_kernel() {
    __shared__ float cs[32], sn[32];
    const int s = blockIdx.x, t = threadIdx.x;
    if (t < 32) {
        double invf = pow(10000.0, -((double)(2 * t)) / 64.0);
        double si, co;
        sincos((double)s * invf, &si, &co);
        cs[t] = (float)co; sn[t] = (float)si;
    }
    __syncthreads();
    for (int p = t; p < 512; p += 256) {
        int hh = p >> 5, i = p & 31;
        int base = s * DM + hh * 64 + i;
        float c = cs[i], si = sn[i];
        float q1 = g_Q[base], q2 = g_Q[base + 32];
        float qa = (q1 * c - q2 * si) * 0.125f;
        float qb = (q2 * c + q1 * si) * 0.125f;
        __nv_bfloat16 h, l;
        split1(qa, h, l); g_qh[base] = h;      g_ql[base] = l;
        split1(qb, h, l); g_qh[base + 32] = h; g_ql[base + 32] = l;
        float k1 = g_K[base], k2 = g_K[base + 32];
        float ka = k1 * c - k2 * si;
        float kb = k2 * c + k1 * si;
        split1(ka, h, l); g_kh[base] = h;      g_kl[base] = l;
        split1(kb, h, l); g_kh[base + 32] = h; g_kl[base + 32] = l;
    }
    for (int i = t; i < DM; i += 256) {
        __nv_bfloat16 h, l;
        split1(g_V[s * DM + i], h, l);
        g_vh[s * DM + i] = h; g_vl[s * DM + i] = l;
    }
}

// ---------------- Flash attention: HMMA split-bf16, causal, online softmax ----
// CTA = (q-tile 128 rows, head). 256 thr / 8 warps; warp = 16 q-rows x full 64 kv.
#define F_QH  0
#define F_QL  18432
#define F_STG 36864            // stage s at F_STG + s*36864: Kh,Kl,Vh,Vl (9216 each)
#define F_T   9216
#define FLASH_SMEM (36864 + 2 * 36864)   // 110592

__device__ __forceinline__ void flash_issue_kv(int t, uint32_t stg, int kbase, int h) {
    const size_t rowoff = (size_t)kbase * DM + h * 64;
    const __nv_bfloat16* srcs[4] = {g_kh + rowoff, g_kl + rowoff, g_vh + rowoff, g_vl + rowoff};
#pragma unroll
    for (int i = 0; i < 8; i++) {
        int idx = t + i * 256;              // 0..2047
        int mat = idx >> 9;                 // 0..3
        int rem = idx & 511;
        int row = rem >> 3, ch = rem & 7;
        cp_async16(stg + mat * F_T + row * SKB + ch * 16,
                   (const char*)srcs[mat] + (size_t)row * (DM * 2) + ch * 16);
    }
    CP_COMMIT();
}

__global__ __launch_bounds__(256)
void flash_kernel() {
    extern __shared__ char dsm[];
    const uint32_t sbase = smem_u32(dsm);
    const int t = threadIdx.x, lane = t & 31, wid = t >> 5;
    const int h = blockIdx.y;
    const int qt = (int)gridDim.x - 1 - (int)blockIdx.x;   // heavy first
    const int qbase = qt * 128;
    const int ntiles = 2 * qt + 2;

    // Q loads (both hi/lo) + tile0, then tile1
    {
        const size_t rowoff = (size_t)qbase * DM + h * 64;
#pragma unroll
        for (int i = 0; i < 8; i++) {
            int idx = t + i * 256;           // 0..2047
            int mat = idx >> 10;             // 0..1 (qh, ql)
            int rem = idx & 1023;
            int row = rem >> 3, ch = rem & 7;
            const __nv_bfloat16* src = (mat == 0 ? g_qh : g_ql) + rowoff;
            cp_async16(sbase + mat * 18432 + row * SKB + ch * 16,
                       (const char*)src + (size_t)row * (DM * 2) + ch * 16);
        }
        flash_issue_kv(t, sbase + F_STG, 0, h);          // shares group with Q
        flash_issue_kv(t, sbase + F_STG + 36864, 64, h); // tile 1
    }

    CP_WAIT1();          // Q + tile0 ready
    __syncthreads();

    // preload Q fragments (persistent)
    const int q = lane >> 3, r = lane & 7;
    uint32_t qhf[4][4], qlf[4][4];
#pragma unroll
    for (int ks = 0; ks < 4; ks++) {
        uint32_t ro = (wid * 16 + (q & 1) * 8 + r) * SKB + (ks * 16 + (q >> 1) * 8) * 2;
        ldsm_x4(qhf[ks], sbase + F_QH + ro);
        ldsm_x4(qlf[ks], sbase + F_QL + ro);
    }

    float o[8][4];
#pragma unroll
    for (int a = 0; a < 8; a++)
#pragma unroll
        for (int b = 0; b < 4; b++) o[a][b] = 0.f;
    float m0r = -1e30f, m1r = -1e30f, l0 = 0.f, l1 = 0.f;

    const int rr = lane >> 2, c2 = (lane & 3) * 2;
    const int qlo = qbase + wid * 16;
    const int qr0 = qlo + rr, qr1 = qr0 + 8;

    for (int kt = 0; kt < ntiles; kt++) {
        // NOTE: data for tile kt already waited on (prologue or end of prev iter)
        const uint32_t stg = sbase + F_STG + (kt & 1) * 36864;

        if (kt * 64 <= qlo + 15) {     // warp tile not fully masked
            float s[8][4];
#pragma unroll
            for (int a = 0; a < 8; a++)
#pragma unroll
                for (int b = 0; b < 4; b++) s[a][b] = 0.f;

            // S = Qh*Kh + Ql*Kh + Qh*Kl
#pragma unroll
            for (int ks = 0; ks < 4; ks++) {
#pragma unroll
                for (int np = 0; np < 4; np++) {
                    uint32_t kf[4];
                    uint32_t ro = (np * 16 + (q >> 1) * 8 + r) * SKB + (ks * 16 + (q & 1) * 8) * 2;
                    ldsm_x4(kf, stg + 0 * F_T + ro);           // Kh
                    mma16816(s[np * 2],     qhf[ks], &kf[0]);
                    mma16816(s[np * 2 + 1], qhf[ks], &kf[2]);
                    mma16816(s[np * 2],     qlf[ks], &kf[0]);
                    mma16816(s[np * 2 + 1], qlf[ks], &kf[2]);
                    ldsm_x4(kf, stg + 1 * F_T + ro);           // Kl
                    mma16816(s[np * 2],     qhf[ks], &kf[0]);
                    mma16816(s[np * 2 + 1], qhf[ks], &kf[2]);
                }
            }

            // causal mask (diagonal-straddling tiles only)
            if (kt * 64 + 63 > qlo) {
#pragma unroll
                for (int nb = 0; nb < 8; nb++) {
                    int kc = kt * 64 + nb * 8 + c2;
                    if (kc     > qr0) s[nb][0] = -1e30f;
                    if (kc + 1 > qr0) s[nb][1] = -1e30f;
                    if (kc     > qr1) s[nb][2] = -1e30f;
                    if (kc + 1 > qr1) s[nb][3] = -1e30f;
                }
            }

            // online softmax (rows: slot0 = regs 0,1; slot1 = regs 2,3)
            float mx0 = -1e30f, mx1 = -1e30f;
#pragma unroll
            for (int nb = 0; nb < 8; nb++) {
                mx0 = fmaxf(mx0, fmaxf(s[nb][0], s[nb][1]));
                mx1 = fmaxf(mx1, fmaxf(s[nb][2], s[nb][3]));
            }
            mx0 = fmaxf(mx0, __shfl_xor_sync(0xffffffffu, mx0, 1));
            mx0 = fmaxf(mx0, __shfl_xor_sync(0xffffffffu, mx0, 2));
            mx1 = fmaxf(mx1, __shfl_xor_sync(0xffffffffu, mx1, 1));
            mx1 = fmaxf(mx1, __shfl_xor_sync(0xffffffffu, mx1, 2));
            float mn0 = fmaxf(m0r, mx0), mn1 = fmaxf(m1r, mx1);
            float al0 = __expf(m0r - mn0), al1 = __expf(m1r - mn1);
            float sum0 = 0.f, sum1 = 0.f;
#pragma unroll
            for (int nb = 0; nb < 8; nb++) {
                s[nb][0] = __expf(s[nb][0] - mn0); sum0 += s[nb][0];
                s[nb][1] = __expf(s[nb][1] - mn0); sum0 += s[nb][1];
                s[nb][2] = __expf(s[nb][2] - mn1); sum1 += s[nb][2];
                s[nb][3] = __expf(s[nb][3] - mn1); sum1 += s[nb][3];
            }
            sum0 += __shfl_xor_sync(0xffffffffu, sum0, 1);
            sum0 += __shfl_xor_sync(0xffffffffu, sum0, 2);
            sum1 += __shfl_xor_sync(0xffffffffu, sum1, 1);
            sum1 += __shfl_xor_sync(0xffffffffu, sum1, 2);
            l0 = l0 * al0 + sum0;  l1 = l1 * al1 + sum1;
            m0r = mn0;  m1r = mn1;
#pragma unroll
            for (int nb = 0; nb < 8; nb++) {
                o[nb][0] *= al0; o[nb][1] *= al0;
                o[nb][2] *= al1; o[nb][3] *= al1;
            }

            // PV: O += (Ph+Pl)*Vh + Ph*Vl
#pragma unroll
            for (int ks = 0; ks < 4; ks++) {
                uint32_t ph[4], pl[4];
#pragma unroll
                for (int half = 0; half < 2; half++) {
                    int nb = 2 * ks + half;
                    __nv_bfloat16 h0, e0, h1, e1, h2, e2, h3, e3;
                    split1(s[nb][0], h0, e0); split1(s[nb][1], h1, e1);
                    split1(s[nb][2], h2, e2); split1(s[nb][3], h3, e3);
                    ph[half * 2]     = pack2(h0, h1);
                    ph[half * 2 + 1] = pack2(h2, h3);
                    pl[half * 2]     = pack2(e0, e1);
                    pl[half * 2 + 1] = pack2(e2, e3);
                }
#pragma unroll
                for (int dp = 0; dp < 4; dp++) {
                    uint32_t vf[4];
                    uint32_t ro = (ks * 16 + (q & 1) * 8 + r) * SKB + (dp * 16 + (q >> 1) * 8) * 2;
                    ldsm_x4t(vf, stg + 2 * F_T + ro);          // Vh
                    mma16816(o[dp * 2],     ph, &vf[0]);
                    mma16816(o[dp * 2 + 1], ph, &vf[2]);
                    mma16816(o[dp * 2],     pl, &vf[0]);
                    mma16816(o[dp * 2 + 1], pl, &vf[2]);
                    ldsm_x4t(vf, stg + 3 * F_T + ro);          // Vl
                    mma16816(o[dp * 2],     ph, &vf[0]);
                    mma16816(o[dp * 2 + 1], ph, &vf[2]);
                }
            }
        }

        __syncthreads();          // done reading this stage
        if (kt + 2 < ntiles)
            flash_issue_kv(t, sbase + F_STG + (kt & 1) * 36864, (kt + 2) * 64, h);
        if (kt + 1 < ntiles) {
            if (kt + 2 < ntiles) { CP_WAIT1(); } else { CP_WAIT0(); }
            __syncthreads();      // tile kt+1 data visible to all
        }
    }

    // epilogue: normalize, split hi/lo, store bf16x2
    float inv0 = 1.f / l0, inv1 = 1.f / l1;
#pragma unroll
    for (int nb = 0; nb < 8; nb++) {
        int col = h * 64 + nb * 8 + c2;
        __nv_bfloat16 h0, e0, h1, e1;
        split1(o[nb][0] * inv0, h0, e0);
        split1(o[nb][1] * inv0, h1, e1);
        *(uint32_t*)&g_ah[(size_t)qr0 * DM + col] = pack2(h0, h1);
        *(uint32_t*)&g_al[(size_t)qr0 * DM + col] = pack2(e0, e1);
        split1(o[nb][2] * inv1, h0, e0);
        split1(o[nb][3] * inv1, h1, e1);
        *(uint32_t*)&g_ah[(size_t)qr1 * DM + col] = pack2(h0, h1);
        *(uint32_t*)&g_al[(size_t)qr1 * DM + col] = pack2(e0, e1);
    }
}

// ---------------- launch ----------------
extern "C" void kernel_launch(void* const* d_in, const int* in_sizes, int n_in,
                              void* d_out, int out_size) {
    const float* x  = (const float*)d_in[0];
    const float* Wq = (const float*)d_in[1];
    const float* Wk = (const float*)d_in[2];
    const float* Wv = (const float*)d_in[3];
    const float* Wo = (const float*)d_in[4];
    float* out = (float*)d_out;

    cudaFuncSetAttribute(mma_gemm_kernel, cudaFuncAttributeMaxDynamicSharedMemorySize, GEMM_SMEM);
    cudaFuncSetAttribute(flash_kernel,   cudaFuncAttributeMaxDynamicSharedMemorySize, FLASH_SMEM);

    cvt_kernel<<<SEQ * DM / 1024, 256>>>(x, 0);
    cvt_kernel<<<DM * DM / 1024, 256>>>(Wq, 1);
    cvt_kernel<<<DM * DM / 1024, 256>>>(Wk, 2);
    cvt_kernel<<<DM * DM / 1024, 256>>>(Wv, 3);
    cvt_kernel<<<DM * DM / 1024, 256>>>(Wo, 4);

    mma_gemm_kernel<<<dim3(3 * DM / 128, SEQ / 128), 128, GEMM_SMEM>>>(0, nullptr);

    rope_cvt_kernel<<<SEQ, 256>>>();

    flash_kernel<<<dim3(SEQ / 128, NH), 256, FLASH_SMEM>>>();

    mma_gemm_kernel<<<dim3(DM / 128, SEQ / 128), 128, GEMM_SMEM>>>(1, out);
}